// round 1
// baseline (speedup 1.0000x reference)
#include <cuda_runtime.h>
#include <math.h>

#define BOXN 128
#define GRID_G (BOXN * BOXN * BOXN)   // 2097152
#define WR 8
#define DIA 17
#define CELLS (DIA * DIA * DIA)       // 4913
#define EPS_IN 6.5f
#define EPS_OUT 79.0f
#define KAPPA02 0.106f
#define CHARGE_CONV 7046.52f
#define N_ITER 30

// Scratch (B=2 fixed by the problem's setup_inputs)
__device__ float g_phi[2 * GRID_G];      // Jacobi ping-pong partner
__device__ float g_invden[2 * GRID_G];   // precomputed 1/denominator

// ---------------------------------------------------------------------------
// Stage 1: accumulate sum of log1p(-rho) per channel into the eps region.
// One block per (batch, atom, channel); 4913 stencil cells per block.
// ---------------------------------------------------------------------------
__global__ void eps_accum_kernel(const float* __restrict__ coords,
                                 const float* __restrict__ params,
                                 const int*   __restrict__ num_atoms,
                                 float* __restrict__ acc, int N)
{
    int blk  = blockIdx.x;
    int ch   = blk & 3;
    int an   = blk >> 2;
    int atom = an % N;
    int b    = an / N;
    if (atom >= num_atoms[b]) return;

    const float* cp = coords + ((size_t)b * N + atom) * 3;
    float x = cp[0], y = cp[1], z = cp[2];
    float radius = params[((size_t)b * N + atom) * 2 + 1];

    float offx = (ch == 0) ? 0.5f : 0.0f;
    float offy = (ch == 1) ? 0.5f : 0.0f;
    float offz = (ch == 2) ? 0.5f : 0.0f;
    float R = radius + ((ch == 3) ? 1.0f : 1.4f);

    // jnp.round == round-half-even == rintf
    int i0x = (int)rintf(x - offx);
    int i0y = (int)rintf(y - offy);
    int i0z = (int)rintf(z - offz);

    float* a = acc + (size_t)(b * 4 + ch) * GRID_G;

    for (int t = threadIdx.x; t < CELLS; t += blockDim.x) {
        int dz = t % DIA;
        int dy = (t / DIA) % DIA;
        int dx = t / (DIA * DIA);
        int ix = i0x + dx - WR;
        int iy = i0y + dy - WR;
        int iz = i0z + dz - WR;
        if ((unsigned)ix >= BOXN || (unsigned)iy >= BOXN || (unsigned)iz >= BOXN)
            continue;
        float px = (float)ix + offx - x;
        float py = (float)iy + offy - y;
        float pz = (float)iz + offz - z;
        float r  = sqrtf(px * px + py * py + pz * pz + 1e-12f);
        float rho = 0.5f * (1.0f - erff((r - R) * 0.5f));   // /ASIGMA, ASIGMA=2
        rho = fminf(fmaxf(rho, 0.0f), 1.0f - 1e-6f);
        float logv = log1pf(-rho);
        atomicAdd(a + ((size_t)ix * BOXN + iy) * BOXN + iz, logv);
    }
}

// ---------------------------------------------------------------------------
// Stage 2: trilinear charge scatter (q). One thread per atom.
// ---------------------------------------------------------------------------
__global__ void q_scatter_kernel(const float* __restrict__ coords,
                                 const float* __restrict__ params,
                                 const int*   __restrict__ num_atoms,
                                 float* __restrict__ q, int N, int B)
{
    int idx = blockIdx.x * blockDim.x + threadIdx.x;
    if (idx >= B * N) return;
    int b = idx / N, n = idx % N;
    if (n >= num_atoms[b]) return;

    const float* cp = coords + (size_t)idx * 3;
    float x = cp[0], y = cp[1], z = cp[2];
    float chg = params[(size_t)idx * 2] * CHARGE_CONV;

    float fx = floorf(x), fy = floorf(y), fz = floorf(z);
    int ix = (int)fx, iy = (int)fy, iz = (int)fz;
    float wx1 = x - fx, wy1 = y - fy, wz1 = z - fz;
    float* qb = q + (size_t)b * GRID_G;

    #pragma unroll
    for (int c = 0; c < 8; c++) {
        int cx = (c >> 2) & 1, cy = (c >> 1) & 1, cz = c & 1;
        int gx = ix + cx, gy = iy + cy, gz = iz + cz;
        if ((unsigned)gx >= BOXN || (unsigned)gy >= BOXN || (unsigned)gz >= BOXN)
            continue;
        float w = (cx ? wx1 : 1.0f - wx1) *
                  (cy ? wy1 : 1.0f - wy1) *
                  (cz ? wz1 : 1.0f - wz1);
        atomicAdd(qb + ((size_t)gx * BOXN + gy) * BOXN + gz, w * chg);
    }
}

// ---------------------------------------------------------------------------
// Stage 3a: acc -> eps, in place.  layout index i = (b*4+c)*G + cell
// ---------------------------------------------------------------------------
__global__ void eps_finalize_kernel(float* __restrict__ eps, int total)
{
    int i = blockIdx.x * blockDim.x + threadIdx.x;
    if (i >= total) return;
    int c = (i / GRID_G) & 3;
    float e = expf(eps[i]);
    eps[i] = (c < 3) ? (1.0f - e) * (EPS_IN - EPS_OUT) + EPS_OUT : (1.0f - e);
}

// ---------------------------------------------------------------------------
// Stage 3b: precompute 1/denominator
// ---------------------------------------------------------------------------
__global__ void invden_kernel(const float* __restrict__ eps,
                              float* __restrict__ invden)
{
    int k = threadIdx.x;   // z
    int j = blockIdx.x;    // y
    int i = blockIdx.y;    // x
    int b = blockIdx.z;
    size_t cell = ((size_t)i * BOXN + j) * BOXN + k;
    const float* ex = eps + (size_t)(b * 4) * GRID_G;
    const float* ey = ex + GRID_G;
    const float* ez = ey + GRID_G;
    const float* lm = ez + GRID_G;
    float d = ex[cell] + ey[cell] + ez[cell] + KAPPA02 * lm[cell];
    if (i > 0) d += ex[cell - BOXN * BOXN];
    if (j > 0) d += ey[cell - BOXN];
    if (k > 0) d += ez[cell - 1];
    invden[(size_t)b * GRID_G + cell] = 1.0f / d;
}

// ---------------------------------------------------------------------------
// Stage 4: one Jacobi sweep (7-point, variable coefficients, zero boundary)
// ---------------------------------------------------------------------------
__global__ void jacobi_kernel(const float* __restrict__ src,
                              float*       __restrict__ dst,
                              const float* __restrict__ eps,
                              const float* __restrict__ rhs,
                              const float* __restrict__ invden)
{
    int k = threadIdx.x;   // z
    int j = blockIdx.x;    // y
    int i = blockIdx.y;    // x
    int b = blockIdx.z;
    size_t cell = ((size_t)i * BOXN + j) * BOXN + k;
    size_t base = (size_t)b * GRID_G + cell;

    const float* ex = eps + (size_t)(b * 4) * GRID_G;
    const float* ey = ex + GRID_G;
    const float* ez = ey + GRID_G;
    const float* ph = src + (size_t)b * GRID_G;

    float num = rhs[base];
    if (i < BOXN - 1) num += ex[cell]               * ph[cell + BOXN * BOXN];
    if (i > 0)        num += ex[cell - BOXN * BOXN] * ph[cell - BOXN * BOXN];
    if (j < BOXN - 1) num += ey[cell]               * ph[cell + BOXN];
    if (j > 0)        num += ey[cell - BOXN]        * ph[cell - BOXN];
    if (k < BOXN - 1) num += ez[cell]               * ph[cell + 1];
    if (k > 0)        num += ez[cell - 1]           * ph[cell - 1];

    dst[base] = num * invden[base];
}

// ---------------------------------------------------------------------------
extern "C" void kernel_launch(void* const* d_in, const int* in_sizes, int n_in,
                              void* d_out, int out_size)
{
    const float* coords    = (const float*)d_in[0];
    const float* params    = (const float*)d_in[1];
    const int*   num_atoms = (const int*)d_in[2];

    int B = in_sizes[2];
    int N = in_sizes[1] / (2 * B);

    float* out = (float*)d_out;
    float* q   = out;                            // [B, 128,128,128]
    float* eps = out + (size_t)B * GRID_G;       // [B, 4, 128,128,128]
    float* phi = eps + (size_t)B * 4 * GRID_G;   // [B, 128,128,128]

    float *phiA, *invden;
    cudaGetSymbolAddress((void**)&phiA, g_phi);
    cudaGetSymbolAddress((void**)&invden, g_invden);

    // Zero entire output: q/eps accumulators and initial phi (Jacobi start).
    cudaMemsetAsync(d_out, 0, (size_t)out_size * sizeof(float), 0);

    eps_accum_kernel<<<B * N * 4, 256>>>(coords, params, num_atoms, eps, N);
    q_scatter_kernel<<<(B * N + 255) / 256, 256>>>(coords, params, num_atoms, q, N, B);

    int total = B * 4 * GRID_G;
    eps_finalize_kernel<<<(total + 255) / 256, 256>>>(eps, total);

    dim3 grid(BOXN, BOXN, B);
    invden_kernel<<<grid, BOXN>>>(eps, invden);

    // Ping-pong: start src = phi (zeroed). 30 sweeps -> final write lands in phi.
    float* src = phi;
    float* dst = phiA;
    for (int it = 0; it < N_ITER; it++) {
        jacobi_kernel<<<grid, BOXN>>>(src, dst, eps, q, invden);
        float* t = src; src = dst; dst = t;
    }
}